// round 5
// baseline (speedup 1.0000x reference)
#include <cuda_runtime.h>

// Problem constants
#define S_LEN   1024
#define DK      64
#define BH      96
#define M_TILE  64
#define NTHREADS 256

#define CTX_ELEMS  ((size_t)BH * S_LEN * DK)        // 6,291,456
#define ATTN_ELEMS ((size_t)BH * S_LEN * S_LEN)     // 100,663,296

// Mask dtype mode, set by detector kernel: 0=int32, 1=float32, 2=uint8
__device__ int g_mask_mode;

__global__ void detect_mask_kernel(const unsigned int* __restrict__ m) {
    int lane = threadIdx.x;
    unsigned no = 0, nf = 0, ni = 0;
    for (int i = lane; i < 1024; i += 32) {
        unsigned w = m[i];
        if (w == 0u) continue;
        if (w == 0x3F800000u) nf = 1;
        else if (w == 1u)     ni = 1;
        else                  no = 1;
    }
    unsigned bno = __ballot_sync(0xFFFFFFFFu, no != 0);
    unsigned bnf = __ballot_sync(0xFFFFFFFFu, nf != 0);
    unsigned bni = __ballot_sync(0xFFFFFFFFu, ni != 0);
    if (lane == 0) {
        int mode;
        if (bno)              mode = 2;   // bytes pack >1 word values -> uint8 bools
        else if (bnf && !bni) mode = 1;   // only 0.0f/1.0f patterns -> float32
        else                  mode = 0;   // only 0/1 ints -> int32
        g_mask_mode = mode;
    }
}

__device__ __forceinline__ unsigned f2tf(float f) {
    unsigned u;
    asm("cvt.rna.tf32.f32 %0, %1;" : "=r"(u) : "f"(f));
    return u;
}

__device__ __forceinline__ void mma_tf32(float c[4], const unsigned a[4],
                                         unsigned b0, unsigned b1) {
    asm volatile(
        "mma.sync.aligned.m16n8k8.row.col.f32.tf32.tf32.f32 "
        "{%0,%1,%2,%3}, {%4,%5,%6,%7}, {%8,%9}, {%0,%1,%2,%3};\n"
        : "+f"(c[0]), "+f"(c[1]), "+f"(c[2]), "+f"(c[3])
        : "r"(a[0]), "r"(a[1]), "r"(a[2]), "r"(a[3]), "r"(b0), "r"(b1));
}

// Fused masked attention:
//   pass 1: S = QK^T/8, p = mask?0:exp(S) -> unnormalized attn to GMEM + row sums
//   pass 2: read attn tile back (L1/L2 hot), *1/rowsum, rewrite, P@V via MMA
__global__ __launch_bounds__(NTHREADS)
void attn_kernel(const float* __restrict__ Q, const float* __restrict__ K,
                 const float* __restrict__ V, const void* __restrict__ maskp,
                 float* __restrict__ ctx_out, float* __restrict__ attn_out)
{
    // K tiles use stride 68 (banks (4n+kk)%32 unique for B-frags),
    // V tiles use stride 72 (banks (8kk+n)%32 unique for B-frags),
    // P tiles use stride 68 (banks (4g+t)%32 unique for A-frags). All conflict-free.
    __shared__ __align__(16) unsigned s_kv[64 * 72];   // K (pass1) / V (pass2)
    __shared__ __align__(16) unsigned s_p[64 * 68];    // normalized P (tf32 bits)
    __shared__ float s_rowsum[64];
    __shared__ float s_inv[64];

    const int tid  = threadIdx.x;
    const int w    = tid >> 5;
    const int lane = tid & 31;
    const int mr   = w & 3;        // row group: rows mr*16 .. +15
    const int nc   = w >> 2;       // col group: cols nc*32 .. +31
    const int g    = lane >> 2;    // groupID
    const int t    = lane & 3;     // threadID-in-group
    const int bh    = blockIdx.y;
    const int qbase = blockIdx.x * M_TILE;
    const int mode  = g_mask_mode;

    const size_t qkv_base = (size_t)bh * S_LEN * DK;
    const size_t attn_bh  = (size_t)bh * S_LEN * S_LEN;

    const unsigned char* mu8  = (const unsigned char*)maskp;
    const int*           mi32 = (const int*)maskp;
    const float*         mf32 = (const float*)maskp;

    // ---- Q A-fragments (tf32), reused for every key tile -------------------
    unsigned qa[8][4];
    {
        const float* Qp = Q + qkv_base + (size_t)(qbase + mr * 16) * DK;
        #pragma unroll
        for (int ki = 0; ki < 8; ++ki) {
            int c0 = ki * 8 + t;
            qa[ki][0] = f2tf(Qp[g * DK + c0]);
            qa[ki][1] = f2tf(Qp[(g + 8) * DK + c0]);
            qa[ki][2] = f2tf(Qp[g * DK + c0 + 4]);
            qa[ki][3] = f2tf(Qp[(g + 8) * DK + c0 + 4]);
        }
    }

    if (tid < 64) s_rowsum[tid] = 0.f;

    const int row0  = mr * 16 + g;       // CTA-relative row of c0/c1
    const int grow0 = qbase + row0;      // absolute q row
    float rs0 = 0.f, rs1 = 0.f;

    // ======================= PASS 1 ========================================
    for (int kt = 0; kt < 16; ++kt) {
        __syncthreads();
        {   // stage K tile [64 keys x 64 d] as tf32 bits, stride 68
            const float* Kp = K + qkv_base + (size_t)(kt * 64) * DK;
            #pragma unroll
            for (int i = 0; i < 4; ++i) {
                int fidx = i * NTHREADS + tid;
                int r = fidx >> 4, c4 = (fidx & 15) * 4;
                float4 v = *(const float4*)(Kp + r * DK + c4);
                *(uint4*)&s_kv[r * 68 + c4] =
                    make_uint4(f2tf(v.x), f2tf(v.y), f2tf(v.z), f2tf(v.w));
            }
        }
        __syncthreads();

        float sc[4][4];
        #pragma unroll
        for (int j = 0; j < 4; ++j) { sc[j][0]=0.f; sc[j][1]=0.f; sc[j][2]=0.f; sc[j][3]=0.f; }

        #pragma unroll
        for (int ki = 0; ki < 8; ++ki) {
            int kk = ki * 8 + t;
            #pragma unroll
            for (int j = 0; j < 4; ++j) {
                int n = nc * 32 + j * 8 + g;
                unsigned b0 = s_kv[n * 68 + kk];
                unsigned b1 = s_kv[n * 68 + kk + 4];
                mma_tf32(sc[j], qa[ki], b0, b1);
            }
        }

        // epilogue: mask, exp, unnormalized-attn store, row-sum accumulation
        #pragma unroll
        for (int j = 0; j < 4; ++j) {
            int col = kt * 64 + nc * 32 + j * 8 + 2 * t;
            size_t off0 = attn_bh + (size_t)grow0 * S_LEN + col;
            size_t off1 = off0 + (size_t)8 * S_LEN;
            unsigned m0, m1, m2, m3;
            if (mode == 2) {
                m0 = mu8[off0]; m1 = mu8[off0 + 1];
                m2 = mu8[off1]; m3 = mu8[off1 + 1];
            } else if (mode == 0) {
                m0 = (unsigned)mi32[off0]; m1 = (unsigned)mi32[off0 + 1];
                m2 = (unsigned)mi32[off1]; m3 = (unsigned)mi32[off1 + 1];
            } else {
                m0 = (mf32[off0]     != 0.f); m1 = (mf32[off0 + 1] != 0.f);
                m2 = (mf32[off1]     != 0.f); m3 = (mf32[off1 + 1] != 0.f);
            }
            float p0 = m0 ? 0.f : __expf(sc[j][0] * 0.125f);
            float p1 = m1 ? 0.f : __expf(sc[j][1] * 0.125f);
            float p2 = m2 ? 0.f : __expf(sc[j][2] * 0.125f);
            float p3 = m3 ? 0.f : __expf(sc[j][3] * 0.125f);
            rs0 += p0 + p1;
            rs1 += p2 + p3;
            *(float2*)(attn_out + off0) = make_float2(p0, p1);
            *(float2*)(attn_out + off1) = make_float2(p2, p3);
        }
    }

    // row-sum reduce: quad (same row) -> smem across the 2 col-group warps
    rs0 += __shfl_xor_sync(0xFFFFFFFFu, rs0, 1);
    rs0 += __shfl_xor_sync(0xFFFFFFFFu, rs0, 2);
    rs1 += __shfl_xor_sync(0xFFFFFFFFu, rs1, 1);
    rs1 += __shfl_xor_sync(0xFFFFFFFFu, rs1, 2);
    if (t == 0) {
        atomicAdd(&s_rowsum[row0], rs0);
        atomicAdd(&s_rowsum[row0 + 8], rs1);
    }
    __syncthreads();
    if (tid < 64) s_inv[tid] = 1.0f / s_rowsum[tid];
    __syncthreads();

    // ======================= PASS 2 ========================================
    float oc[4][4];
    #pragma unroll
    for (int j = 0; j < 4; ++j) { oc[j][0]=0.f; oc[j][1]=0.f; oc[j][2]=0.f; oc[j][3]=0.f; }

    for (int kt = 0; kt < 16; ++kt) {
        __syncthreads();
        {   // stage V tile [64 keys x 64 d] as tf32 bits, stride 72
            const float* Vp = V + qkv_base + (size_t)(kt * 64) * DK;
            #pragma unroll
            for (int i = 0; i < 4; ++i) {
                int fidx = i * NTHREADS + tid;
                int r = fidx >> 4, c4 = (fidx & 15) * 4;
                float4 v = *(const float4*)(Vp + r * DK + c4);
                *(uint4*)&s_kv[r * 72 + c4] =
                    make_uint4(f2tf(v.x), f2tf(v.y), f2tf(v.z), f2tf(v.w));
            }
        }
        {   // read back unnormalized attn tile (hot in L1/L2), normalize,
            // rewrite to GMEM, stash tf32 copy for the PV MMA
            float* Ap = attn_out + attn_bh + (size_t)qbase * S_LEN + kt * 64;
            #pragma unroll
            for (int i = 0; i < 4; ++i) {
                int fidx = i * NTHREADS + tid;
                int r = fidx >> 4, c4 = (fidx & 15) * 4;
                float4 p4 = *(float4*)(Ap + (size_t)r * S_LEN + c4);
                float iv = s_inv[r];
                p4.x *= iv; p4.y *= iv; p4.z *= iv; p4.w *= iv;
                *(float4*)(Ap + (size_t)r * S_LEN + c4) = p4;
                *(uint4*)&s_p[r * 68 + c4] =
                    make_uint4(f2tf(p4.x), f2tf(p4.y), f2tf(p4.z), f2tf(p4.w));
            }
        }
        __syncthreads();

        #pragma unroll
        for (int ki = 0; ki < 8; ++ki) {
            int kk = ki * 8 + t;
            unsigned a[4];
            a[0] = s_p[(mr * 16 + g) * 68 + kk];
            a[1] = s_p[(mr * 16 + g + 8) * 68 + kk];
            a[2] = s_p[(mr * 16 + g) * 68 + kk + 4];
            a[3] = s_p[(mr * 16 + g + 8) * 68 + kk + 4];
            #pragma unroll
            for (int j = 0; j < 4; ++j) {
                int n = nc * 32 + j * 8 + g;
                unsigned b0 = s_kv[kk * 72 + n];
                unsigned b1 = s_kv[(kk + 4) * 72 + n];
                mma_tf32(oc[j], a, b0, b1);
            }
        }
    }

    // ---- write context -----------------------------------------------------
    const size_t cb = qkv_base + (size_t)grow0 * DK;
    #pragma unroll
    for (int j = 0; j < 4; ++j) {
        int dcol = nc * 32 + j * 8 + 2 * t;
        *(float2*)(ctx_out + cb + dcol)          = make_float2(oc[j][0], oc[j][1]);
        *(float2*)(ctx_out + cb + 8 * DK + dcol) = make_float2(oc[j][2], oc[j][3]);
    }
}

extern "C" void kernel_launch(void* const* d_in, const int* in_sizes, int n_in,
                              void* d_out, int out_size) {
    const float* Q = (const float*)d_in[0];
    const float* K = (const float*)d_in[1];
    const float* V = (const float*)d_in[2];
    const void*  M = d_in[3];

    float* ctx  = (float*)d_out;                 // tuple order: (context, attn)
    float* attn = (float*)d_out + CTX_ELEMS;

    detect_mask_kernel<<<1, 32>>>((const unsigned int*)M);

    dim3 grid(S_LEN / M_TILE, BH);               // (16, 96)
    attn_kernel<<<grid, NTHREADS>>>(Q, K, V, M, ctx, attn);
}